// round 9
// baseline (speedup 1.0000x reference)
#include <cuda_runtime.h>
#include <cuda_bf16.h>

// LSTMHead, round 9.
//
// Kernel 1 (gates): flat-stream producer. Each warp owns 4 consecutive rows
//   = a linear stream of 32 float4-chunks; a depth-6 ring buffer keeps 6
//   LDG.128 in flight per warp at all times (32 warps/SM x 6 x 128B = 24.6KB
//   in-flight per SM == DRAM saturation requirement). Accumulators are
//   shuffle-reduced and stored at each row boundary (every 8 chunks).
// Kernel 2 (scan): unchanged from R8 (proven): 4096 chunks of 8 steps,
//   48 burn-in, one chunk per lane, 128 single-warp blocks.
//   tanh.approx activations; sigmoid gates pre-scaled by 0.5.

#define SEQ   32768
#define DIM   1024
#define CHUNK 8
#define BURN  48
#define NCHUNK (SEQ / CHUNK)        // 4096
#define CWARPS (NCHUNK / 32)        // 128
#define TROWS  (SEQ / CHUNK)        // 4096

#define ROWS_PER_WARP 4
#define PBLOCKS (SEQ / (8 * ROWS_PER_WARP))   // 1024
#define NSTREAM (8 * ROWS_PER_WARP)           // 32 chunks per warp stream
#define DEPTH 6                                // ring-buffer depth

// transposed, pre-scaled gate pre-activations (512 KB, L2-resident)
__device__ float4 g_gatesT[SEQ];

__device__ __forceinline__ int gidx(int t) {
    return (t & (CHUNK - 1)) * TROWS + (t >> 3);
}

// ---------------------------------------------------------------------------
// Kernel 1: gates GEMV, flat-stream with depth-6 LDG pipeline.
// ---------------------------------------------------------------------------
__global__ __launch_bounds__(256, 4) void gates_kernel(
    const float* __restrict__ x,
    const float* __restrict__ W_ih,
    const float* __restrict__ b_ih,
    const float* __restrict__ b_hh)
{
    __shared__ float4 sW[4][DIM / 4];   // 16 KB

    const int tid = threadIdx.x;
    const float4* W4 = reinterpret_cast<const float4*>(W_ih);
    for (int i = tid; i < DIM; i += 256) {
        sW[i >> 8][i & 255] = W4[i];
    }

    const float bb0 = b_ih[0] + b_hh[0];
    const float bb1 = b_ih[1] + b_hh[1];
    const float bb2 = b_ih[2] + b_hh[2];
    const float bb3 = b_ih[3] + b_hh[3];
    __syncthreads();

    const int warp = tid >> 5;
    const int lane = tid & 31;
    const int row0 = (blockIdx.x * 8 + warp) * ROWS_PER_WARP;

    // warp's flat stream: 32 chunks of 32 float4 (4 rows x 8 chunks)
    const float4* xs =
        reinterpret_cast<const float4*>(x) + (size_t)row0 * (DIM / 4);

    float4 buf[DEPTH];
#pragma unroll
    for (int i = 0; i < DEPTH; ++i) buf[i] = __ldg(&xs[i * 32 + lane]);

    float a0 = 0.f, a1 = 0.f, a2 = 0.f, a3 = 0.f;

#pragma unroll
    for (int i = 0; i < NSTREAM; ++i) {
        const float4 v = buf[i % DEPTH];
        if (i + DEPTH < NSTREAM)
            buf[i % DEPTH] = __ldg(&xs[(i + DEPTH) * 32 + lane]);

        const int idx = (i & 7) * 32 + lane;
        const float4 w0 = sW[0][idx];
        const float4 w1 = sW[1][idx];
        const float4 w2 = sW[2][idx];
        const float4 w3 = sW[3][idx];

        a0 = fmaf(v.x, w0.x, fmaf(v.y, w0.y, fmaf(v.z, w0.z, fmaf(v.w, w0.w, a0))));
        a1 = fmaf(v.x, w1.x, fmaf(v.y, w1.y, fmaf(v.z, w1.z, fmaf(v.w, w1.w, a1))));
        a2 = fmaf(v.x, w2.x, fmaf(v.y, w2.y, fmaf(v.z, w2.z, fmaf(v.w, w2.w, a2))));
        a3 = fmaf(v.x, w3.x, fmaf(v.y, w3.y, fmaf(v.z, w3.z, fmaf(v.w, w3.w, a3))));

        if ((i & 7) == 7) {
            // row boundary: reduce + store, reset accumulators
#pragma unroll
            for (int off = 16; off > 0; off >>= 1) {
                a0 += __shfl_xor_sync(0xffffffffu, a0, off);
                a1 += __shfl_xor_sync(0xffffffffu, a1, off);
                a2 += __shfl_xor_sync(0xffffffffu, a2, off);
                a3 += __shfl_xor_sync(0xffffffffu, a3, off);
            }
            if (lane == 0) {
                const int row = row0 + (i >> 3);
                g_gatesT[gidx(row)] = make_float4(
                    0.5f * (a0 + bb0), 0.5f * (a1 + bb1),
                    (a2 + bb2),        0.5f * (a3 + bb3));
            }
            a0 = 0.f; a1 = 0.f; a2 = 0.f; a3 = 0.f;
        }
    }
}

// ---------------------------------------------------------------------------
// Kernel 2: SIMD chunk-parallel scan (unchanged from R8).
// ---------------------------------------------------------------------------
__device__ __forceinline__ float mufu_tanh(float x) {
    float y; asm("tanh.approx.f32 %0, %1;" : "=f"(y) : "f"(x)); return y;
}

// one LSTM step. s = (0.5*gx0, 0.5*gx1, gx2, 0.5*gx3); ws likewise scaled.
__device__ __forceinline__ void lstm_step(
    const float4 s,
    const float ws0, const float ws1, const float ws2, const float ws3,
    float& h, float& c)
{
    const float u0 = fmaf(ws0, h, s.x);
    const float u1 = fmaf(ws1, h, s.y);
    const float u2 = fmaf(ws2, h, s.z);
    const float u3 = fmaf(ws3, h, s.w);

    const float ig = fmaf(0.5f, mufu_tanh(u0), 0.5f);   // sigmoid
    const float fg = fmaf(0.5f, mufu_tanh(u1), 0.5f);   // sigmoid
    const float gc = mufu_tanh(u2);                     // tanh
    const float og = fmaf(0.5f, mufu_tanh(u3), 0.5f);   // sigmoid

    c = fmaf(fg, c, ig * gc);
    h = og * mufu_tanh(c);
}

__global__ __launch_bounds__(32) void scan_kernel(
    const float* __restrict__ W_hh,
    const float* __restrict__ h0,
    const float* __restrict__ c0,
    float* __restrict__ out)
{
    const int lane = threadIdx.x;
    const int cid  = blockIdx.x * 32 + lane;    // chunk id
    const int base = cid * CHUNK - BURN;        // burn start (may be <0)

    const float ws0 = 0.5f * W_hh[0];
    const float ws1 = 0.5f * W_hh[1];
    const float ws2 = W_hh[2];
    const float ws3 = 0.5f * W_hh[3];
    const float h0v = __ldg(h0);
    const float c0v = __ldg(c0);

    float h = 0.f, c = 0.f;

    float4 buf[4], nbuf[4];
#pragma unroll
    for (int k = 0; k < 4; ++k) {
        int t = base + k;
        t = t < 0 ? 0 : t;
        buf[k] = __ldg(&g_gatesT[gidx(t)]);
    }

    // ---- burn-in: 48 steps, no stores ----
#pragma unroll
    for (int jb = 0; jb < BURN; jb += 4) {
#pragma unroll
        for (int k = 0; k < 4; ++k) {
            int t = base + jb + 4 + k;
            t = t < 0 ? 0 : t;
            nbuf[k] = __ldg(&g_gatesT[gidx(t)]);
        }
#pragma unroll
        for (int k = 0; k < 4; ++k)
            lstm_step(buf[k], ws0, ws1, ws2, ws3, h, c);
#pragma unroll
        for (int k = 0; k < 4; ++k) buf[k] = nbuf[k];
    }

    // chunk 0 starts from the true initial state
    if (cid == 0) { h = h0v; c = c0v; }

    // ---- emit 8 steps ----
    const int t_begin = cid * CHUNK;
#pragma unroll
    for (int k = 0; k < 4; ++k)
        nbuf[k] = __ldg(&g_gatesT[gidx(t_begin + 4 + k)]);
#pragma unroll
    for (int k = 0; k < 4; ++k) {
        lstm_step(buf[k], ws0, ws1, ws2, ws3, h, c);
        out[t_begin + k] = h;
    }
#pragma unroll
    for (int k = 0; k < 4; ++k) {
        lstm_step(nbuf[k], ws0, ws1, ws2, ws3, h, c);
        out[t_begin + 4 + k] = h;
    }
}

// ---------------------------------------------------------------------------
extern "C" void kernel_launch(void* const* d_in, const int* in_sizes, int n_in,
                              void* d_out, int out_size)
{
    const float* x    = (const float*)d_in[0];
    const float* W_ih = (const float*)d_in[1];
    const float* W_hh = (const float*)d_in[2];
    const float* b_ih = (const float*)d_in[3];
    const float* b_hh = (const float*)d_in[4];
    const float* h0   = (const float*)d_in[5];
    const float* c0   = (const float*)d_in[6];
    float* out = (float*)d_out;

    gates_kernel<<<PBLOCKS, 256>>>(x, W_ih, b_ih, b_hh);   // 1024 blocks
    scan_kernel<<<CWARPS, 32>>>(W_hh, h0, c0, out);        // 128 warps
}

// round 10
// speedup vs baseline: 1.0078x; 1.0078x over previous
#include <cuda_runtime.h>
#include <cuda_bf16.h>

// LSTMHead, round 10.
//
// Kernel 1 (gates): 4 rows per warp, W read from smem ONCE per j-chunk and
//   shared across all 4 rows -> 8 LDS.128/row (was 16 in R8, 32 in R7/R9).
//   L1TEX wavefronts/row drop 96 -> 64, freeing the shared L1 pipe for the
//   DRAM stream (evidence: R7/R9 with 32 LDS/row were slowest, R8 with 16
//   was fastest -> LDS traffic, not LDG depth, is the binding term).
//   x double-buffered at distance 1 (4 LDG in flight per warp).
// Kernel 2 (scan): unchanged (proven): 4096 chunks of 8 steps, 48 burn-in,
//   one chunk per lane, 128 single-warp blocks. tanh.approx activations;
//   sigmoid(z)=0.5+0.5*tanh(z/2); sigmoid gates pre-scaled by 0.5.

#define SEQ   32768
#define DIM   1024
#define CHUNK 8
#define BURN  48
#define NCHUNK (SEQ / CHUNK)        // 4096
#define CWARPS (NCHUNK / 32)        // 128
#define TROWS  (SEQ / CHUNK)        // 4096

#define RPW 4                        // rows per warp
#define PBLOCKS (SEQ / (8 * RPW))    // 1024

// transposed, pre-scaled gate pre-activations (512 KB, L2-resident)
__device__ float4 g_gatesT[SEQ];

__device__ __forceinline__ int gidx(int t) {
    return (t & (CHUNK - 1)) * TROWS + (t >> 3);
}

// ---------------------------------------------------------------------------
// Kernel 1: gates GEMV, 4 rows/warp with W shared across rows.
// ---------------------------------------------------------------------------
__global__ __launch_bounds__(256, 3) void gates_kernel(
    const float* __restrict__ x,
    const float* __restrict__ W_ih,
    const float* __restrict__ b_ih,
    const float* __restrict__ b_hh)
{
    __shared__ float4 sW[4][DIM / 4];   // 16 KB

    const int tid = threadIdx.x;
    const float4* W4 = reinterpret_cast<const float4*>(W_ih);
    for (int i = tid; i < DIM; i += 256) {
        sW[i >> 8][i & 255] = W4[i];
    }

    const float bb0 = b_ih[0] + b_hh[0];
    const float bb1 = b_ih[1] + b_hh[1];
    const float bb2 = b_ih[2] + b_hh[2];
    const float bb3 = b_ih[3] + b_hh[3];
    __syncthreads();

    const int warp = tid >> 5;
    const int lane = tid & 31;
    const int row0 = (blockIdx.x * 8 + warp) * RPW;

    const float4* xr[RPW];
#pragma unroll
    for (int r = 0; r < RPW; ++r)
        xr[r] = reinterpret_cast<const float4*>(x)
              + (size_t)(row0 + r) * (DIM / 4);

    // double-buffered x chunks for 4 rows (distance-1 prefetch)
    float4 xb[RPW][2];
#pragma unroll
    for (int r = 0; r < RPW; ++r) xb[r][0] = __ldg(&xr[r][lane]);

    float acc[RPW][4];
#pragma unroll
    for (int r = 0; r < RPW; ++r)
#pragma unroll
        for (int g = 0; g < 4; ++g) acc[r][g] = 0.f;

#pragma unroll
    for (int j = 0; j < 8; ++j) {
        const int cur = j & 1, nxt = cur ^ 1;
        if (j < 7) {
#pragma unroll
            for (int r = 0; r < RPW; ++r)
                xb[r][nxt] = __ldg(&xr[r][(j + 1) * 32 + lane]);
        }
        const int idx = j * 32 + lane;
        const float4 w0 = sW[0][idx];
        const float4 w1 = sW[1][idx];
        const float4 w2 = sW[2][idx];
        const float4 w3 = sW[3][idx];

#pragma unroll
        for (int r = 0; r < RPW; ++r) {
            const float4 v = xb[r][cur];
            acc[r][0] = fmaf(v.x, w0.x, fmaf(v.y, w0.y,
                        fmaf(v.z, w0.z, fmaf(v.w, w0.w, acc[r][0]))));
            acc[r][1] = fmaf(v.x, w1.x, fmaf(v.y, w1.y,
                        fmaf(v.z, w1.z, fmaf(v.w, w1.w, acc[r][1]))));
            acc[r][2] = fmaf(v.x, w2.x, fmaf(v.y, w2.y,
                        fmaf(v.z, w2.z, fmaf(v.w, w2.w, acc[r][2]))));
            acc[r][3] = fmaf(v.x, w3.x, fmaf(v.y, w3.y,
                        fmaf(v.z, w3.z, fmaf(v.w, w3.w, acc[r][3]))));
        }
    }

#pragma unroll
    for (int r = 0; r < RPW; ++r) {
#pragma unroll
        for (int off = 16; off > 0; off >>= 1) {
            acc[r][0] += __shfl_xor_sync(0xffffffffu, acc[r][0], off);
            acc[r][1] += __shfl_xor_sync(0xffffffffu, acc[r][1], off);
            acc[r][2] += __shfl_xor_sync(0xffffffffu, acc[r][2], off);
            acc[r][3] += __shfl_xor_sync(0xffffffffu, acc[r][3], off);
        }
        if (lane == 0) {
            g_gatesT[gidx(row0 + r)] = make_float4(
                0.5f * (acc[r][0] + bb0), 0.5f * (acc[r][1] + bb1),
                (acc[r][2] + bb2),        0.5f * (acc[r][3] + bb3));
        }
    }
}

// ---------------------------------------------------------------------------
// Kernel 2: SIMD chunk-parallel scan (unchanged).
// ---------------------------------------------------------------------------
__device__ __forceinline__ float mufu_tanh(float x) {
    float y; asm("tanh.approx.f32 %0, %1;" : "=f"(y) : "f"(x)); return y;
}

// one LSTM step. s = (0.5*gx0, 0.5*gx1, gx2, 0.5*gx3); ws likewise scaled.
__device__ __forceinline__ void lstm_step(
    const float4 s,
    const float ws0, const float ws1, const float ws2, const float ws3,
    float& h, float& c)
{
    const float u0 = fmaf(ws0, h, s.x);
    const float u1 = fmaf(ws1, h, s.y);
    const float u2 = fmaf(ws2, h, s.z);
    const float u3 = fmaf(ws3, h, s.w);

    const float ig = fmaf(0.5f, mufu_tanh(u0), 0.5f);   // sigmoid
    const float fg = fmaf(0.5f, mufu_tanh(u1), 0.5f);   // sigmoid
    const float gc = mufu_tanh(u2);                     // tanh
    const float og = fmaf(0.5f, mufu_tanh(u3), 0.5f);   // sigmoid

    c = fmaf(fg, c, ig * gc);
    h = og * mufu_tanh(c);
}

__global__ __launch_bounds__(32) void scan_kernel(
    const float* __restrict__ W_hh,
    const float* __restrict__ h0,
    const float* __restrict__ c0,
    float* __restrict__ out)
{
    const int lane = threadIdx.x;
    const int cid  = blockIdx.x * 32 + lane;    // chunk id
    const int base = cid * CHUNK - BURN;        // burn start (may be <0)

    const float ws0 = 0.5f * W_hh[0];
    const float ws1 = 0.5f * W_hh[1];
    const float ws2 = W_hh[2];
    const float ws3 = 0.5f * W_hh[3];
    const float h0v = __ldg(h0);
    const float c0v = __ldg(c0);

    float h = 0.f, c = 0.f;

    float4 buf[4], nbuf[4];
#pragma unroll
    for (int k = 0; k < 4; ++k) {
        int t = base + k;
        t = t < 0 ? 0 : t;
        buf[k] = __ldg(&g_gatesT[gidx(t)]);
    }

    // ---- burn-in: 48 steps, no stores ----
#pragma unroll
    for (int jb = 0; jb < BURN; jb += 4) {
#pragma unroll
        for (int k = 0; k < 4; ++k) {
            int t = base + jb + 4 + k;
            t = t < 0 ? 0 : t;
            nbuf[k] = __ldg(&g_gatesT[gidx(t)]);
        }
#pragma unroll
        for (int k = 0; k < 4; ++k)
            lstm_step(buf[k], ws0, ws1, ws2, ws3, h, c);
#pragma unroll
        for (int k = 0; k < 4; ++k) buf[k] = nbuf[k];
    }

    // chunk 0 starts from the true initial state
    if (cid == 0) { h = h0v; c = c0v; }

    // ---- emit 8 steps ----
    const int t_begin = cid * CHUNK;
#pragma unroll
    for (int k = 0; k < 4; ++k)
        nbuf[k] = __ldg(&g_gatesT[gidx(t_begin + 4 + k)]);
#pragma unroll
    for (int k = 0; k < 4; ++k) {
        lstm_step(buf[k], ws0, ws1, ws2, ws3, h, c);
        out[t_begin + k] = h;
    }
#pragma unroll
    for (int k = 0; k < 4; ++k) {
        lstm_step(nbuf[k], ws0, ws1, ws2, ws3, h, c);
        out[t_begin + 4 + k] = h;
    }
}

// ---------------------------------------------------------------------------
extern "C" void kernel_launch(void* const* d_in, const int* in_sizes, int n_in,
                              void* d_out, int out_size)
{
    const float* x    = (const float*)d_in[0];
    const float* W_ih = (const float*)d_in[1];
    const float* W_hh = (const float*)d_in[2];
    const float* b_ih = (const float*)d_in[3];
    const float* b_hh = (const float*)d_in[4];
    const float* h0   = (const float*)d_in[5];
    const float* c0   = (const float*)d_in[6];
    float* out = (float*)d_out;

    gates_kernel<<<PBLOCKS, 256>>>(x, W_ih, b_ih, b_hh);   // 1024 blocks
    scan_kernel<<<CWARPS, 32>>>(W_hh, h0, c0, out);        // 128 warps
}

// round 11
// speedup vs baseline: 1.0612x; 1.0530x over previous
#include <cuda_runtime.h>
#include <cuda_bf16.h>

// LSTMHead, round 11 = R8 (best, 34.8us) + PDL overlap of the scan kernel.
//
// Kernel 1 (gates): byte-identical to R8's winner: each warp computes TWO
//   rows with a j-pipelined inner loop (x double-buffered, W read once per j
//   and shared across the row pair), launch_bounds(256,4), 2048 blocks.
//   Ends with griddepcontrol.launch_dependents (after all gate stores).
// Kernel 2 (scan): unchanged math (4096 chunks x 8 steps, 48 burn-in, one
//   chunk per lane, 128 single-warp blocks), but launched with
//   ProgrammaticStreamSerialization: its prologue overlaps the gates tail,
//   and it griddepcontrol.wait's before the first g_gatesT read.
//   tanh.approx activations; sigmoid(z)=0.5+0.5*tanh(z/2).

#define SEQ   32768
#define DIM   1024
#define CHUNK 8
#define BURN  48
#define NCHUNK (SEQ / CHUNK)        // 4096
#define CWARPS (NCHUNK / 32)        // 128
#define TROWS  (SEQ / CHUNK)        // 4096

// transposed, pre-scaled gate pre-activations (512 KB, L2-resident)
__device__ float4 g_gatesT[SEQ];

__device__ __forceinline__ int gidx(int t) {
    return (t & (CHUNK - 1)) * TROWS + (t >> 3);
}

__device__ __forceinline__ void pdl_trigger() {
    asm volatile("griddepcontrol.launch_dependents;" ::: "memory");
}
__device__ __forceinline__ void pdl_wait() {
    asm volatile("griddepcontrol.wait;" ::: "memory");
}

// ---------------------------------------------------------------------------
// Kernel 1: gates GEMV, 2 rows/warp, j-pipelined (R8 shape).
// ---------------------------------------------------------------------------
__global__ __launch_bounds__(256, 4) void gates_kernel(
    const float* __restrict__ x,
    const float* __restrict__ W_ih,
    const float* __restrict__ b_ih,
    const float* __restrict__ b_hh)
{
    __shared__ float4 sW[4][DIM / 4];   // 16 KB

    const int tid = threadIdx.x;
    const float4* W4 = reinterpret_cast<const float4*>(W_ih);
    for (int i = tid; i < DIM; i += 256) {
        sW[i >> 8][i & 255] = W4[i];
    }
    __syncthreads();

    const int warp = tid >> 5;
    const int lane = tid & 31;
    const int rowA = (blockIdx.x * 8 + warp) * 2;
    const int rowB = rowA + 1;

    const float4* xA =
        reinterpret_cast<const float4*>(x) + (size_t)rowA * (DIM / 4);
    const float4* xB =
        reinterpret_cast<const float4*>(x) + (size_t)rowB * (DIM / 4);

    // double-buffered per-j x loads: 2 LDG continuously in flight per warp
    float4 xa[2], xb[2];
    xa[0] = __ldg(&xA[lane]);
    xb[0] = __ldg(&xB[lane]);

    float a0 = 0.f, a1 = 0.f, a2 = 0.f, a3 = 0.f;
    float e0 = 0.f, e1 = 0.f, e2 = 0.f, e3 = 0.f;

#pragma unroll
    for (int j = 0; j < 8; ++j) {
        const int cur = j & 1, nxt = cur ^ 1;
        if (j < 7) {
            xa[nxt] = __ldg(&xA[(j + 1) * 32 + lane]);
            xb[nxt] = __ldg(&xB[(j + 1) * 32 + lane]);
        }
        const int idx = j * 32 + lane;
        const float4 w0 = sW[0][idx];
        const float4 w1 = sW[1][idx];
        const float4 w2 = sW[2][idx];
        const float4 w3 = sW[3][idx];
        const float4 va = xa[cur];
        const float4 vb = xb[cur];

        a0 = fmaf(va.x, w0.x, fmaf(va.y, w0.y, fmaf(va.z, w0.z, fmaf(va.w, w0.w, a0))));
        a1 = fmaf(va.x, w1.x, fmaf(va.y, w1.y, fmaf(va.z, w1.z, fmaf(va.w, w1.w, a1))));
        a2 = fmaf(va.x, w2.x, fmaf(va.y, w2.y, fmaf(va.z, w2.z, fmaf(va.w, w2.w, a2))));
        a3 = fmaf(va.x, w3.x, fmaf(va.y, w3.y, fmaf(va.z, w3.z, fmaf(va.w, w3.w, a3))));
        e0 = fmaf(vb.x, w0.x, fmaf(vb.y, w0.y, fmaf(vb.z, w0.z, fmaf(vb.w, w0.w, e0))));
        e1 = fmaf(vb.x, w1.x, fmaf(vb.y, w1.y, fmaf(vb.z, w1.z, fmaf(vb.w, w1.w, e1))));
        e2 = fmaf(vb.x, w2.x, fmaf(vb.y, w2.y, fmaf(vb.z, w2.z, fmaf(vb.w, w2.w, e2))));
        e3 = fmaf(vb.x, w3.x, fmaf(vb.y, w3.y, fmaf(vb.z, w3.z, fmaf(vb.w, w3.w, e3))));
    }

#pragma unroll
    for (int off = 16; off > 0; off >>= 1) {
        a0 += __shfl_xor_sync(0xffffffffu, a0, off);
        a1 += __shfl_xor_sync(0xffffffffu, a1, off);
        a2 += __shfl_xor_sync(0xffffffffu, a2, off);
        a3 += __shfl_xor_sync(0xffffffffu, a3, off);
        e0 += __shfl_xor_sync(0xffffffffu, e0, off);
        e1 += __shfl_xor_sync(0xffffffffu, e1, off);
        e2 += __shfl_xor_sync(0xffffffffu, e2, off);
        e3 += __shfl_xor_sync(0xffffffffu, e3, off);
    }
    if (lane == 0) {
        const float bb0 = b_ih[0] + b_hh[0];
        const float bb1 = b_ih[1] + b_hh[1];
        const float bb2 = b_ih[2] + b_hh[2];
        const float bb3 = b_ih[3] + b_hh[3];
        g_gatesT[gidx(rowA)] = make_float4(
            0.5f * (a0 + bb0), 0.5f * (a1 + bb1),
            (a2 + bb2),        0.5f * (a3 + bb3));
        g_gatesT[gidx(rowB)] = make_float4(
            0.5f * (e0 + bb0), 0.5f * (e1 + bb1),
            (e2 + bb2),        0.5f * (e3 + bb3));
    }

    // all of this CTA's gate stores are issued above -> safe to let the
    // dependent scan grid launch.
    pdl_trigger();
}

// ---------------------------------------------------------------------------
// Kernel 2: SIMD chunk-parallel scan (R8 math, PDL-overlapped prologue).
// ---------------------------------------------------------------------------
__device__ __forceinline__ float mufu_tanh(float x) {
    float y; asm("tanh.approx.f32 %0, %1;" : "=f"(y) : "f"(x)); return y;
}

// one LSTM step. s = (0.5*gx0, 0.5*gx1, gx2, 0.5*gx3); ws likewise scaled.
__device__ __forceinline__ void lstm_step(
    const float4 s,
    const float ws0, const float ws1, const float ws2, const float ws3,
    float& h, float& c)
{
    const float u0 = fmaf(ws0, h, s.x);
    const float u1 = fmaf(ws1, h, s.y);
    const float u2 = fmaf(ws2, h, s.z);
    const float u3 = fmaf(ws3, h, s.w);

    const float ig = fmaf(0.5f, mufu_tanh(u0), 0.5f);   // sigmoid
    const float fg = fmaf(0.5f, mufu_tanh(u1), 0.5f);   // sigmoid
    const float gc = mufu_tanh(u2);                     // tanh
    const float og = fmaf(0.5f, mufu_tanh(u3), 0.5f);   // sigmoid

    c = fmaf(fg, c, ig * gc);
    h = og * mufu_tanh(c);
}

__global__ __launch_bounds__(32) void scan_kernel(
    const float* __restrict__ W_hh,
    const float* __restrict__ h0,
    const float* __restrict__ c0,
    float* __restrict__ out)
{
    const int lane = threadIdx.x;
    const int cid  = blockIdx.x * 32 + lane;    // chunk id
    const int base = cid * CHUNK - BURN;        // burn start (may be <0)

    // ---- PDL prologue: everything independent of g_gatesT ----
    const float ws0 = 0.5f * W_hh[0];
    const float ws1 = 0.5f * W_hh[1];
    const float ws2 = W_hh[2];
    const float ws3 = 0.5f * W_hh[3];
    const float h0v = __ldg(h0);
    const float c0v = __ldg(c0);

    // wait for the gates grid's stores to be visible
    pdl_wait();

    float h = 0.f, c = 0.f;

    float4 buf[4], nbuf[4];
#pragma unroll
    for (int k = 0; k < 4; ++k) {
        int t = base + k;
        t = t < 0 ? 0 : t;
        buf[k] = __ldg(&g_gatesT[gidx(t)]);
    }

    // ---- burn-in: 48 steps, no stores ----
#pragma unroll
    for (int jb = 0; jb < BURN; jb += 4) {
#pragma unroll
        for (int k = 0; k < 4; ++k) {
            int t = base + jb + 4 + k;
            t = t < 0 ? 0 : t;
            nbuf[k] = __ldg(&g_gatesT[gidx(t)]);
        }
#pragma unroll
        for (int k = 0; k < 4; ++k)
            lstm_step(buf[k], ws0, ws1, ws2, ws3, h, c);
#pragma unroll
        for (int k = 0; k < 4; ++k) buf[k] = nbuf[k];
    }

    // chunk 0 starts from the true initial state
    if (cid == 0) { h = h0v; c = c0v; }

    // ---- emit 8 steps ----
    const int t_begin = cid * CHUNK;
#pragma unroll
    for (int k = 0; k < 4; ++k)
        nbuf[k] = __ldg(&g_gatesT[gidx(t_begin + 4 + k)]);
#pragma unroll
    for (int k = 0; k < 4; ++k) {
        lstm_step(buf[k], ws0, ws1, ws2, ws3, h, c);
        out[t_begin + k] = h;
    }
#pragma unroll
    for (int k = 0; k < 4; ++k) {
        lstm_step(nbuf[k], ws0, ws1, ws2, ws3, h, c);
        out[t_begin + 4 + k] = h;
    }
}

// ---------------------------------------------------------------------------
extern "C" void kernel_launch(void* const* d_in, const int* in_sizes, int n_in,
                              void* d_out, int out_size)
{
    const float* x    = (const float*)d_in[0];
    const float* W_ih = (const float*)d_in[1];
    const float* W_hh = (const float*)d_in[2];
    const float* b_ih = (const float*)d_in[3];
    const float* b_hh = (const float*)d_in[4];
    const float* h0   = (const float*)d_in[5];
    const float* c0   = (const float*)d_in[6];
    float* out = (float*)d_out;

    gates_kernel<<<SEQ / 16, 256>>>(x, W_ih, b_ih, b_hh);   // 2048 blocks

    // scan launched with Programmatic Dependent Launch: overlaps its
    // prologue with the gates tail; griddepcontrol.wait orders gate reads.
    cudaLaunchConfig_t cfg = {};
    cfg.gridDim  = dim3(CWARPS, 1, 1);
    cfg.blockDim = dim3(32, 1, 1);
    cfg.dynamicSmemBytes = 0;
    cfg.stream = 0;
    cudaLaunchAttribute attrs[1];
    attrs[0].id = cudaLaunchAttributeProgrammaticStreamSerialization;
    attrs[0].val.programmaticStreamSerializationAllowed = 1;
    cfg.attrs = attrs;
    cfg.numAttrs = 1;
    cudaLaunchKernelEx(&cfg, scan_kernel, W_hh, h0, c0, (float*)out);
}